// round 7
// baseline (speedup 1.0000x reference)
#include <cuda_runtime.h>
#include <cuda_bf16.h>
#include <math.h>

#define TT 512
#define BB 32
#define HH 512
#define NROWS 16384
#define LDK 544            // 514 padded to /16
#define NG 4096
#define GP 80              // GEMM smem pitch (bytes): 64B data + 16B pad

__device__ __nv_bfloat16 g_xb[(size_t)NROWS * LDK];
__device__ __nv_bfloat16 g_wb[(size_t)NG * LDK];
__device__ float         g_bias[NG];
__device__ float         g_pre[(size_t)NROWS * NG];
// h layout: [dir][t][g(32)][b(32)][16]
__device__ __nv_bfloat16 g_hs[(size_t)2 * TT * BB * HH];
__device__ float         g_em[(size_t)NROWS * 6];
__device__ int           g_flags[64 * 256];    // per-producer flags, 1KB apart

static __device__ __forceinline__ unsigned packbf(float lo, float hi) {
    __nv_bfloat162 v = __floats2bfloat162_rn(lo, hi);
    return *reinterpret_cast<unsigned*>(&v);
}

static __device__ __forceinline__ void mma_bf16(float& c0, float& c1, float& c2, float& c3,
                                                unsigned a0, unsigned a1, unsigned a2, unsigned a3,
                                                unsigned b0, unsigned b1) {
    asm volatile(
        "mma.sync.aligned.m16n8k16.row.col.f32.bf16.bf16.f32 "
        "{%0,%1,%2,%3},{%4,%5,%6,%7},{%8,%9},{%0,%1,%2,%3};"
        : "+f"(c0), "+f"(c1), "+f"(c2), "+f"(c3)
        : "r"(a0), "r"(a1), "r"(a2), "r"(a3), "r"(b0), "r"(b1));
}

static __device__ __forceinline__ float fsig(float x) {
    return __frcp_rn(1.f + __expf(-x));
}
static __device__ __forceinline__ float ftanh(float x) {
    float t = __expf(2.f * x);
    return (t - 1.f) * __frcp_rn(t + 1.f);
}

// ---- K1: x = [emb[ids] | eeg[:,:,4:6] | pad] -> bf16 [t*32+b][544] ---------
__global__ void build_x_k(const int* __restrict__ ids, const float* __restrict__ eeg,
                          const float* __restrict__ emb) {
    int row = blockIdx.x, t = row >> 5, b = row & 31;
    int id = ids[b * TT + t];
    const float* er = emb + (size_t)id * 512;
    __nv_bfloat16* xr = g_xb + (size_t)row * LDK;
    for (int d = threadIdx.x; d < LDK; d += blockDim.x) {
        float v;
        if (d < 512)      v = er[d];
        else if (d < 514) v = eeg[((size_t)(b * TT + t)) * 8 + 4 + (d - 512)];
        else              v = 0.f;
        xr[d] = __float2bfloat16(v);
    }
}

// ---- K1b: pack W_ih both dirs -> bf16 [4096][544], bias f32, reset flags ---
__global__ void pack_w_k(const float* __restrict__ wf, const float* __restrict__ wb,
                         const float* __restrict__ bf, const float* __restrict__ bbv) {
    int r = blockIdx.x;
    if (threadIdx.x == 0 && r < 64) g_flags[r * 256] = 0;
    const float* src = (r < 2048) ? (wf + (size_t)r * 514) : (wb + (size_t)(r - 2048) * 514);
    __nv_bfloat16* dst = g_wb + (size_t)r * LDK;
    for (int d = threadIdx.x; d < LDK; d += blockDim.x)
        dst[d] = __float2bfloat16((d < 514) ? src[d] : 0.f);
    if (threadIdx.x == 0) g_bias[r] = (r < 2048) ? bf[r] : bbv[r - 2048];
}

// ---- K2: pre = x @ W^T + bias. cp.async double-buffered, ldmatrix frags ----
__global__ void __launch_bounds__(256) gemm_pre_k() {
    __shared__ __align__(16) unsigned char As[2][128 * GP];
    __shared__ __align__(16) unsigned char Bs[2][128 * GP];
    const int tid = threadIdx.x;
    const int bn = blockIdx.x * 128, bm = blockIdx.y * 128;
    const int w = tid >> 5, l = tid & 31;
    const int wm = (w & 1) * 64, wn = (w >> 1) * 32;
    float acc[4][4][4];
#pragma unroll
    for (int i = 0; i < 4; i++)
#pragma unroll
        for (int j = 0; j < 4; j++)
#pragma unroll
            for (int k = 0; k < 4; k++) acc[i][j][k] = 0.f;

    const int cr = tid >> 2, cc = (tid & 3) * 16;    // copy: row, 16B chunk
    const char* Ag = (const char*)g_xb + (size_t)(bm + cr) * (LDK * 2) + cc;
    const char* Bg = (const char*)g_wb + (size_t)(bn + cr) * (LDK * 2) + cc;
    const unsigned sA = (unsigned)__cvta_generic_to_shared(&As[0][0]);
    const unsigned sB = (unsigned)__cvta_generic_to_shared(&Bs[0][0]);
    const unsigned dA0 = sA + cr * GP + cc;
    const unsigned dB0 = sB + cr * GP + cc;

#define GEMM_ISSUE(buf, kt) do {                                                   \
        unsigned da = dA0 + (buf) * (128 * GP);                                    \
        unsigned db = dB0 + (buf) * (128 * GP);                                    \
        const char* ga = Ag + (kt) * 64;                                           \
        const char* gb = Bg + (kt) * 64;                                           \
        asm volatile("cp.async.cg.shared.global [%0],[%1],16;" :: "r"(da), "l"(ga));\
        asm volatile("cp.async.cg.shared.global [%0],[%1],16;"                     \
                     :: "r"(da + 64 * GP), "l"(ga + (size_t)64 * (LDK * 2)));      \
        asm volatile("cp.async.cg.shared.global [%0],[%1],16;" :: "r"(db), "l"(gb));\
        asm volatile("cp.async.cg.shared.global [%0],[%1],16;"                     \
                     :: "r"(db + 64 * GP), "l"(gb + (size_t)64 * (LDK * 2)));      \
        asm volatile("cp.async.commit_group;");                                    \
    } while (0)

    GEMM_ISSUE(0, 0);
    const unsigned lmA = (unsigned)((l & 15) * GP + (l >> 4) * 16);
    const unsigned lmB = (unsigned)((((l & 7) + ((l >> 4) << 3))) * GP + ((l >> 3) & 1) * 16);

    for (int kt = 0; kt < 17; kt++) {
        const int buf = kt & 1;
        if (kt < 16) {
            GEMM_ISSUE(buf ^ 1, kt + 1);
            asm volatile("cp.async.wait_group 1;");
        } else {
            asm volatile("cp.async.wait_group 0;");
        }
        __syncthreads();
        const unsigned baseA = sA + buf * (128 * GP);
        const unsigned baseB = sB + buf * (128 * GP);
#pragma unroll
        for (int h16 = 0; h16 < 2; h16++) {
            unsigned af[4][4], bfr[4][2];
#pragma unroll
            for (int mt = 0; mt < 4; mt++) {
                unsigned addr = baseA + (unsigned)((wm + mt * 16) * GP + h16 * 32) + lmA;
                asm volatile("ldmatrix.sync.aligned.m8n8.x4.shared.b16 {%0,%1,%2,%3},[%4];"
                             : "=r"(af[mt][0]), "=r"(af[mt][1]), "=r"(af[mt][2]), "=r"(af[mt][3])
                             : "r"(addr));
            }
#pragma unroll
            for (int pr = 0; pr < 2; pr++) {
                unsigned addr = baseB + (unsigned)((wn + pr * 16) * GP + h16 * 32) + lmB;
                asm volatile("ldmatrix.sync.aligned.m8n8.x4.shared.b16 {%0,%1,%2,%3},[%4];"
                             : "=r"(bfr[2*pr][0]), "=r"(bfr[2*pr][1]),
                               "=r"(bfr[2*pr+1][0]), "=r"(bfr[2*pr+1][1])
                             : "r"(addr));
            }
#pragma unroll
            for (int mt = 0; mt < 4; mt++)
#pragma unroll
                for (int nf = 0; nf < 4; nf++)
                    mma_bf16(acc[mt][nf][0], acc[mt][nf][1], acc[mt][nf][2], acc[mt][nf][3],
                             af[mt][0], af[mt][1], af[mt][2], af[mt][3],
                             bfr[nf][0], bfr[nf][1]);
        }
        __syncthreads();
    }
#pragma unroll
    for (int mt = 0; mt < 4; mt++) {
        int m0 = bm + wm + mt * 16 + (l >> 2);
#pragma unroll
        for (int nf = 0; nf < 4; nf++) {
            int n0 = bn + wn + nf * 8 + ((l & 3) << 1);
            float2 bv2 = *(const float2*)&g_bias[n0];
            float2 o0 = make_float2(acc[mt][nf][0] + bv2.x, acc[mt][nf][1] + bv2.y);
            float2 o1 = make_float2(acc[mt][nf][2] + bv2.x, acc[mt][nf][3] + bv2.y);
            *(float2*)(g_pre + (size_t)m0 * NG + n0)       = o0;
            *(float2*)(g_pre + (size_t)(m0 + 8) * NG + n0) = o1;
        }
    }
}

// ---- K3: persistent BiLSTM; distributed flag barrier (no RMW) --------------
__global__ void __launch_bounds__(256, 1) lstm_mma_k(const float* __restrict__ whhf,
                                                     const float* __restrict__ whhb) {
    __shared__ __align__(16) unsigned char Ab[32 * 1040];
    __shared__ float gsm[64][33];
    const int tid = threadIdx.x, cta = blockIdx.x;
    const int dir = cta >> 5, g = cta & 31;
    const int w = tid >> 5, l = tid & 31;

    const int nloc = w * 8 + (l >> 2);
    const int Gn = nloc >> 4, jn = nloc & 15;
    const float* Wrow = (dir ? whhb : whhf) + (size_t)(Gn * 512 + g * 16 + jn) * 512;
    unsigned Bf0[32], Bf1[32];
#pragma unroll
    for (int ks = 0; ks < 32; ks++) {
        const float* p = Wrow + ks * 16 + ((l & 3) << 1);
        Bf0[ks] = packbf(p[0], p[1]);
        Bf1[ks] = packbf(p[8], p[9]);
    }
    const int jj = tid & 15, b0g = tid >> 4;
    float cs0 = 0.f, cs1 = 0.f;

    const unsigned ab_base = (unsigned)__cvta_generic_to_shared(Ab);
    const unsigned lm_off = (unsigned)((l & 15) * 1040 + (l >> 4) * 16);
    const int* myflag_set = g_flags + (size_t)(dir * 32 + l) * 256;  // lane->producer
    int* myflag = g_flags + (size_t)cta * 256;

    for (int step = 0; step < TT; step++) {
        const int t = dir ? (TT - 1 - step) : step;
        const float* pp = g_pre + ((size_t)t * BB) * NG + dir * 2048 + g * 16 + jj;
        float pg[2][4];
#pragma unroll
        for (int pi = 0; pi < 2; pi++) {
            int b = b0g + pi * 16;
#pragma unroll
            for (int Gi = 0; Gi < 4; Gi++)
                pg[pi][Gi] = __ldg(pp + (size_t)b * NG + Gi * 512);
        }
        float acc[2][4] = {{0.f,0.f,0.f,0.f},{0.f,0.f,0.f,0.f}};
        if (step > 0) {
            const int tp = dir ? (t + 1) : (t - 1);
            // per-warp poll: lane l watches producer (dir*32+l)'s flag
            {
                int v;
                do {
                    asm volatile("ld.acquire.gpu.global.b32 %0, [%1];"
                                 : "=r"(v) : "l"(myflag_set) : "memory");
                } while (__any_sync(0xffffffffu, v < step));
            }
            const uint4* src = (const uint4*)(g_hs + ((size_t)dir * TT + tp) * 16384);
            for (int i = tid; i < 2048; i += 256) {
                int cr = i >> 1, half = i & 1;
                int bsrc = cr & 31, gg = cr >> 5;
                *(uint4*)(Ab + bsrc * 1040 + gg * 32 + half * 16) = __ldcg(src + i);
            }
            __syncthreads();
#pragma unroll
            for (int ks = 0; ks < 32; ks++) {
#pragma unroll
                for (int mt = 0; mt < 2; mt++) {
                    unsigned a0, a1, a2, a3;
                    unsigned addr = ab_base + (unsigned)(mt * 16 * 1040 + ks * 32) + lm_off;
                    asm volatile("ldmatrix.sync.aligned.m8n8.x4.shared.b16 {%0,%1,%2,%3},[%4];"
                                 : "=r"(a0), "=r"(a1), "=r"(a2), "=r"(a3) : "r"(addr));
                    mma_bf16(acc[mt][0], acc[mt][1], acc[mt][2], acc[mt][3],
                             a0, a1, a2, a3, Bf0[ks], Bf1[ks]);
                }
            }
        }
        {
            const int rr = w * 8 + ((l & 3) << 1);
            const int bb_ = l >> 2;
#pragma unroll
            for (int mt = 0; mt < 2; mt++) {
                gsm[rr    ][mt * 16 + bb_    ] = acc[mt][0];
                gsm[rr + 1][mt * 16 + bb_    ] = acc[mt][1];
                gsm[rr    ][mt * 16 + bb_ + 8] = acc[mt][2];
                gsm[rr + 1][mt * 16 + bb_ + 8] = acc[mt][3];
            }
        }
        __syncthreads();
        __nv_bfloat16* hdst = g_hs + (((size_t)dir * TT + t) * 32 + g) * 512 + jj;
#pragma unroll
        for (int pi = 0; pi < 2; pi++) {
            int b = b0g + pi * 16;
            float gi = gsm[jj     ][b] + pg[pi][0];
            float gf = gsm[16 + jj][b] + pg[pi][1];
            float gg = gsm[32 + jj][b] + pg[pi][2];
            float go = gsm[48 + jj][b] + pg[pi][3];
            float si = fsig(gi), sf = fsig(gf), so = fsig(go);
            float& cs = pi ? cs1 : cs0;
            cs = sf * cs + si * ftanh(gg);
            float h = so * ftanh(cs);
            hdst[b * 16] = __float2bfloat16(h);
        }
        __syncthreads();   // all h-stores ordered before the release store
        if (tid == 0)
            asm volatile("st.release.gpu.global.b32 [%0], %1;"
                         :: "l"(myflag), "r"(step + 1) : "memory");
    }
}

// ---- K4: LayerNorm(1024) + ReLU + emission; h layout [dir][t][g][b][16] ----
__global__ void __launch_bounds__(256) ln_emit_k(const float* __restrict__ lng,
                                                 const float* __restrict__ lnb,
                                                 const float* __restrict__ wout,
                                                 const float* __restrict__ bout) {
    __shared__ float sh[1024];
    __shared__ float rs[8], rs2[8];
    __shared__ float s_mu, s_rstd;
    const int row = blockIdx.x, tid = threadIdx.x;
    const int lane = tid & 31, w = tid >> 5;
    const int t = row >> 5, b = row & 31;
    const __nv_bfloat16* hf = g_hs + ((size_t)t * 32) * 512 + b * 16;
    const __nv_bfloat16* hb = g_hs + ((size_t)TT + t) * 32 * 512 + b * 16;
    float s = 0.f, s2 = 0.f;
#pragma unroll
    for (int i = 0; i < 4; i++) {
        int idx = tid + i * 256;
        int d = idx & 511;
        int gg = d >> 4, jjv = d & 15;
        float x = (idx < 512) ? __bfloat162float(hf[gg * 512 + jjv])
                              : __bfloat162float(hb[gg * 512 + jjv]);
        sh[idx] = x; s += x; s2 += x * x;
    }
    for (int o = 16; o; o >>= 1) {
        s  += __shfl_down_sync(0xffffffffu, s, o);
        s2 += __shfl_down_sync(0xffffffffu, s2, o);
    }
    if (!lane) { rs[w] = s; rs2[w] = s2; }
    __syncthreads();
    if (!tid) {
        float S = 0.f, S2 = 0.f;
        for (int i = 0; i < 8; i++) { S += rs[i]; S2 += rs2[i]; }
        float mu = S * (1.f / 1024.f);
        s_mu = mu;
        s_rstd = rsqrtf(S2 * (1.f / 1024.f) - mu * mu + 1e-5f);
    }
    __syncthreads();
    float mu = s_mu, rstd = s_rstd;
#pragma unroll
    for (int i = 0; i < 4; i++) {
        int idx = tid + i * 256;
        float x = (sh[idx] - mu) * rstd * lng[idx] + lnb[idx];
        sh[idx] = fmaxf(x, 0.f);
    }
    __syncthreads();
    if (w < 6) {
        float acc = 0.f;
        for (int i = lane; i < 1024; i += 32) acc = fmaf(sh[i], wout[w * 1024 + i], acc);
        for (int o = 16; o; o >>= 1) acc += __shfl_down_sync(0xffffffffu, acc, o);
        if (!lane) g_em[(size_t)row * 6 + w] = acc + bout[w];
    }
}

// ---- K5: CRF (numerator + forward algorithm + mean). mask is int32. --------
__global__ void crf_k(const int* __restrict__ tags, const int* __restrict__ mask,
                      const float* __restrict__ st, const float* __restrict__ en,
                      const float* __restrict__ tr, float* __restrict__ out) {
    __shared__ float ll[32];
    const unsigned full = 0xffffffffu;
    const int b = threadIdx.x >> 5, j = threadIdx.x & 31;
    const bool act = j < 6;
    float trc[6];
#pragma unroll
    for (int i = 0; i < 6; i++) trc[i] = tr[i * 6 + (act ? j : 0)];
    float alpha = act ? (st[j] + g_em[b * 6 + j]) : -1e30f;
    int prev = tags[b * TT];
    float score = st[prev] + g_em[b * 6 + prev];
    int cnt = (mask[b * TT] != 0) ? 1 : 0;
    for (int t = 1; t < TT; t++) {
        float m = (mask[b * TT + t] != 0) ? 1.f : 0.f;
        cnt += (int)m;
        int tg = tags[b * TT + t];
        const float* emt = g_em + ((size_t)t * BB + b) * 6;
        score += m * (tr[prev * 6 + tg] + emt[tg]);
        prev = tg;
        float av[6];
#pragma unroll
        for (int i = 0; i < 6; i++) av[i] = __shfl_sync(full, alpha, i);
        if (act) {
            float mx = -1e30f;
#pragma unroll
            for (int i = 0; i < 6; i++) mx = fmaxf(mx, av[i] + trc[i]);
            float sm = 0.f;
#pragma unroll
            for (int i = 0; i < 6; i++) sm += expf(av[i] + trc[i] - mx);
            float nxt = mx + logf(sm) + emt[j];
            if (m > 0.f) alpha = nxt;
        }
    }
    int ltag = tags[b * TT + (cnt - 1)];
    float num = score + en[ltag];
    float v = act ? (alpha + en[j]) : -1e30f;
    float mx = v;
    for (int o = 16; o; o >>= 1) mx = fmaxf(mx, __shfl_xor_sync(full, mx, o));
    float sm = act ? expf(v - mx) : 0.f;
    for (int o = 16; o; o >>= 1) sm += __shfl_xor_sync(full, sm, o);
    float den = mx + logf(sm);
    if (j == 0) ll[b] = num - den;
    __syncthreads();
    if (threadIdx.x == 0) {
        float s = 0.f;
        for (int i = 0; i < 32; i++) s += ll[i];
        *out = -s * (1.f / 32.f);
    }
}

extern "C" void kernel_launch(void* const* d_in, const int* in_sizes, int n_in,
                              void* d_out, int out_size) {
    const int*   ids  = (const int*)  d_in[0];
    const float* eeg  = (const float*)d_in[1];
    const int*   tags = (const int*)  d_in[2];
    const int*   mask = (const int*)  d_in[3];
    const float* emb  = (const float*)d_in[4];
    const float* wihf = (const float*)d_in[5];
    const float* whhf = (const float*)d_in[6];
    const float* bf   = (const float*)d_in[7];
    const float* wihb = (const float*)d_in[8];
    const float* whhb = (const float*)d_in[9];
    const float* bb   = (const float*)d_in[10];
    const float* lng  = (const float*)d_in[11];
    const float* lnb  = (const float*)d_in[12];
    const float* wout = (const float*)d_in[13];
    const float* bout = (const float*)d_in[14];
    const float* st   = (const float*)d_in[15];
    const float* en   = (const float*)d_in[16];
    const float* tr   = (const float*)d_in[17];
    float* out = (float*)d_out;

    build_x_k<<<NROWS, 128>>>(ids, eeg, emb);
    pack_w_k<<<NG, 128>>>(wihf, wihb, bf, bb);
    gemm_pre_k<<<dim3(32, 128), 256>>>();
    lstm_mma_k<<<64, 256>>>(whhf, whhb);
    ln_emit_k<<<NROWS, 256>>>(lng, lnb, wout, bout);
    crf_k<<<1, 1024>>>(tags, mask, st, en, tr, out);
}

// round 8
// speedup vs baseline: 1.0133x; 1.0133x over previous
#include <cuda_runtime.h>
#include <cuda_bf16.h>
#include <math.h>

#define TT 512
#define BB 32
#define HH 512
#define NROWS 16384
#define LDK 544            // 514 padded to /16
#define NG 4096

__device__ __nv_bfloat16 g_xb[(size_t)NROWS * LDK];
__device__ __nv_bfloat16 g_wb[(size_t)NG * LDK];
__device__ float         g_bias[NG];
__device__ float         g_pre[(size_t)NROWS * NG];
// h layout: [dir][t][bh(2)][g(16)][b(16)][32]  (1KB per CTA chunk)
__device__ __nv_bfloat16 g_hs[(size_t)2 * TT * 2 * 8192];
__device__ float         g_em[(size_t)NROWS * 6];
__device__ int           g_flags[64 * 256];    // per-producer flags, 1KB apart

static __device__ __forceinline__ unsigned packbf(float lo, float hi) {
    __nv_bfloat162 v = __floats2bfloat162_rn(lo, hi);
    return *reinterpret_cast<unsigned*>(&v);
}

static __device__ __forceinline__ void mma_bf16(float& c0, float& c1, float& c2, float& c3,
                                                unsigned a0, unsigned a1, unsigned a2, unsigned a3,
                                                unsigned b0, unsigned b1) {
    asm volatile(
        "mma.sync.aligned.m16n8k16.row.col.f32.bf16.bf16.f32 "
        "{%0,%1,%2,%3},{%4,%5,%6,%7},{%8,%9},{%0,%1,%2,%3};"
        : "+f"(c0), "+f"(c1), "+f"(c2), "+f"(c3)
        : "r"(a0), "r"(a1), "r"(a2), "r"(a3), "r"(b0), "r"(b1));
}

static __device__ __forceinline__ float fsig(float x) {
    return __frcp_rn(1.f + __expf(-x));
}
static __device__ __forceinline__ float ftanh(float x) {
    float t = __expf(2.f * x);
    return (t - 1.f) * __frcp_rn(t + 1.f);
}

// ---- K1: x = [emb[ids] | eeg[:,:,4:6] | pad] -> bf16 [t*32+b][544] ---------
__global__ void build_x_k(const int* __restrict__ ids, const float* __restrict__ eeg,
                          const float* __restrict__ emb) {
    int row = blockIdx.x, t = row >> 5, b = row & 31;
    int id = ids[b * TT + t];
    const float* er = emb + (size_t)id * 512;
    __nv_bfloat16* xr = g_xb + (size_t)row * LDK;
    for (int d = threadIdx.x; d < LDK; d += blockDim.x) {
        float v;
        if (d < 512)      v = er[d];
        else if (d < 514) v = eeg[((size_t)(b * TT + t)) * 8 + 4 + (d - 512)];
        else              v = 0.f;
        xr[d] = __float2bfloat16(v);
    }
}

// ---- K1b: pack W_ih both dirs -> bf16 [4096][544], bias f32, reset flags ---
__global__ void pack_w_k(const float* __restrict__ wf, const float* __restrict__ wb,
                         const float* __restrict__ bf, const float* __restrict__ bbv) {
    int r = blockIdx.x;
    if (threadIdx.x == 0 && r < 64) g_flags[r * 256] = 0;
    const float* src = (r < 2048) ? (wf + (size_t)r * 514) : (wb + (size_t)(r - 2048) * 514);
    __nv_bfloat16* dst = g_wb + (size_t)r * LDK;
    for (int d = threadIdx.x; d < LDK; d += blockDim.x)
        dst[d] = __float2bfloat16((d < 514) ? src[d] : 0.f);
    if (threadIdx.x == 0) g_bias[r] = (r < 2048) ? bf[r] : bbv[r - 2048];
}

// ---- K2: pre = x @ W^T + bias. 64x64 tile, 128 thr, high occupancy ---------
__global__ void __launch_bounds__(128) gemm_pre_k() {
    __shared__ __align__(16) unsigned char As[64 * 48];
    __shared__ __align__(16) unsigned char Bs[64 * 48];
    const int tid = threadIdx.x;
    const int bn = blockIdx.x * 64, bm = blockIdx.y * 64;
    const int w = tid >> 5, l = tid & 31;
    const int wm = (w & 1) * 32, wn = (w >> 1) * 32;
    float acc[2][4][4];
#pragma unroll
    for (int i = 0; i < 2; i++)
#pragma unroll
        for (int j = 0; j < 4; j++)
#pragma unroll
            for (int k = 0; k < 4; k++) acc[i][j][k] = 0.f;

    const int lr = tid >> 1, lh = (tid & 1) * 16;
    const char* Aptr = (const char*)(g_xb + (size_t)(bm + lr) * LDK) + lh;
    const char* Bptr = (const char*)(g_wb + (size_t)(bn + lr) * LDK) + lh;
    uint4 av = *(const uint4*)(Aptr);
    uint4 bv = *(const uint4*)(Bptr);

    for (int kt = 0; kt < 34; kt++) {
        *(uint4*)(As + lr * 48 + lh) = av;
        *(uint4*)(Bs + lr * 48 + lh) = bv;
        __syncthreads();
        if (kt < 33) {
            av = *(const uint4*)(Aptr + (kt + 1) * 32);
            bv = *(const uint4*)(Bptr + (kt + 1) * 32);
        }
        unsigned af[2][4], bfr[4][2];
#pragma unroll
        for (int mt = 0; mt < 2; mt++) {
            const unsigned char* p = As + (wm + mt * 16 + (l >> 2)) * 48 + ((l & 3) << 2);
            af[mt][0] = *(const unsigned*)(p);
            af[mt][1] = *(const unsigned*)(p + 8 * 48);
            af[mt][2] = *(const unsigned*)(p + 16);
            af[mt][3] = *(const unsigned*)(p + 8 * 48 + 16);
        }
#pragma unroll
        for (int nf = 0; nf < 4; nf++) {
            const unsigned char* p = Bs + (wn + nf * 8 + (l >> 2)) * 48 + ((l & 3) << 2);
            bfr[nf][0] = *(const unsigned*)(p);
            bfr[nf][1] = *(const unsigned*)(p + 16);
        }
#pragma unroll
        for (int mt = 0; mt < 2; mt++)
#pragma unroll
            for (int nf = 0; nf < 4; nf++)
                mma_bf16(acc[mt][nf][0], acc[mt][nf][1], acc[mt][nf][2], acc[mt][nf][3],
                         af[mt][0], af[mt][1], af[mt][2], af[mt][3],
                         bfr[nf][0], bfr[nf][1]);
        __syncthreads();
    }
#pragma unroll
    for (int mt = 0; mt < 2; mt++) {
        int m0 = bm + wm + mt * 16 + (l >> 2);
#pragma unroll
        for (int nf = 0; nf < 4; nf++) {
            int n0 = bn + wn + nf * 8 + ((l & 3) << 1);
            float2 bv2 = *(const float2*)&g_bias[n0];
            float2 o0 = make_float2(acc[mt][nf][0] + bv2.x, acc[mt][nf][1] + bv2.y);
            float2 o1 = make_float2(acc[mt][nf][2] + bv2.x, acc[mt][nf][3] + bv2.y);
            *(float2*)(g_pre + (size_t)m0 * NG + n0)       = o0;
            *(float2*)(g_pre + (size_t)(m0 + 8) * NG + n0) = o1;
        }
    }
}

// ---- K3: persistent BiLSTM; 4 groups (dir x batch-half) x 16 CTAs ----------
// CTA owns 32 h-dims x 4 gates (128 W rows) for 16 batches. Consumers stage
// only their group's 16KB h and wait on 16 producers.
__global__ void __launch_bounds__(256, 1) lstm_mma_k(const float* __restrict__ whhf,
                                                     const float* __restrict__ whhb) {
    __shared__ __align__(16) unsigned char Ab[16 * 1040];
    __shared__ float gsm[128][17];
    const int tid = threadIdx.x, cta = blockIdx.x;
    const int grp = cta >> 4, g = cta & 15;
    const int dir = grp >> 1, bh = grp & 1;
    const int w = tid >> 5, l = tid & 31;

    // B fragments: warp owns 16 rows (rloc = w*16 + nf*8 + (l>>2))
    const float* W = dir ? whhb : whhf;
    unsigned Bf[32][2][2];
    {
#pragma unroll
        for (int nf = 0; nf < 2; nf++) {
            int rloc = w * 16 + nf * 8 + (l >> 2);
            int gate = rloc >> 5, jloc = rloc & 31;
            const float* Wr = W + (size_t)(gate * 512 + g * 32 + jloc) * 512;
#pragma unroll
            for (int ks = 0; ks < 32; ks++) {
                const float* p = Wr + ks * 16 + ((l & 3) << 1);
                Bf[ks][nf][0] = packbf(p[0], p[1]);
                Bf[ks][nf][1] = packbf(p[8], p[9]);
            }
        }
    }
    const int dim = tid & 31, brow = tid >> 5;   // gate-phase mapping
    float cs0 = 0.f, cs1 = 0.f;

    const unsigned ab_base = (unsigned)__cvta_generic_to_shared(Ab);
    const unsigned lm_off = (unsigned)((l & 15) * 1040 + (l >> 4) * 16);
    const int* flag_watch = g_flags + (size_t)(grp * 16 + (l & 15)) * 256;
    int* myflag = g_flags + (size_t)cta * 256;

    for (int step = 0; step < TT; step++) {
        const int t = dir ? (TT - 1 - step) : step;
        // prefetch pre-activations (independent of the barrier)
        const float* pp = g_pre + ((size_t)(t * 32 + bh * 16 + brow)) * NG
                        + dir * 2048 + g * 32 + dim;
        float pg[2][4];
#pragma unroll
        for (int pi = 0; pi < 2; pi++) {
#pragma unroll
            for (int Gi = 0; Gi < 4; Gi++)
                pg[pi][Gi] = __ldg(pp + (size_t)pi * 8 * NG + Gi * 512);
        }
        float acc[2][4] = {{0.f,0.f,0.f,0.f},{0.f,0.f,0.f,0.f}};
        if (step > 0) {
            const int tp = dir ? (t + 1) : (t - 1);
            {   // wait for the 16 producers of this group
                int v;
                do {
                    asm volatile("ld.acquire.gpu.global.b32 %0, [%1];"
                                 : "=r"(v) : "l"(flag_watch) : "memory");
                } while (__any_sync(0xffffffffu, v < step));
            }
            // stage group h[tp] (16KB): chunk gg -> Ab[b][k = gg*32 + ...]
            const uint4* src = (const uint4*)(g_hs + (((size_t)dir * TT + tp) * 2 + bh) * 8192);
            for (int i = tid; i < 1024; i += 256) {
                int gg = i >> 6, rem = i & 63;
                int b = rem >> 2, q = rem & 3;
                *(uint4*)(Ab + b * 1040 + gg * 64 + q * 16) = __ldcg(src + i);
            }
            __syncthreads();
#pragma unroll
            for (int ks = 0; ks < 32; ks++) {
                unsigned a0, a1, a2, a3;
                unsigned addr = ab_base + (unsigned)(ks * 32) + lm_off;
                asm volatile("ldmatrix.sync.aligned.m8n8.x4.shared.b16 {%0,%1,%2,%3},[%4];"
                             : "=r"(a0), "=r"(a1), "=r"(a2), "=r"(a3) : "r"(addr));
#pragma unroll
                for (int nf = 0; nf < 2; nf++)
                    mma_bf16(acc[nf][0], acc[nf][1], acc[nf][2], acc[nf][3],
                             a0, a1, a2, a3, Bf[ks][nf][0], Bf[ks][nf][1]);
            }
        }
        // scatter C: gsm[n=row][m=batch]
        {
            const int m0 = l >> 2;
#pragma unroll
            for (int nf = 0; nf < 2; nf++) {
                int n0 = w * 16 + nf * 8 + ((l & 3) << 1);
                gsm[n0    ][m0    ] = acc[nf][0];
                gsm[n0 + 1][m0    ] = acc[nf][1];
                gsm[n0    ][m0 + 8] = acc[nf][2];
                gsm[n0 + 1][m0 + 8] = acc[nf][3];
            }
        }
        __syncthreads();
        // gates: thread -> (dim, brow) and (dim, brow+8)
        __nv_bfloat16* hdst = g_hs + ((((size_t)dir * TT + t) * 2 + bh)) * 8192
                            + g * 512 + dim;
#pragma unroll
        for (int pi = 0; pi < 2; pi++) {
            int m = brow + pi * 8;
            float gi = gsm[dim      ][m] + pg[pi][0];
            float gf = gsm[32 + dim ][m] + pg[pi][1];
            float gg = gsm[64 + dim ][m] + pg[pi][2];
            float go = gsm[96 + dim ][m] + pg[pi][3];
            float si = fsig(gi), sf = fsig(gf), so = fsig(go);
            float& cs = pi ? cs1 : cs0;
            cs = sf * cs + si * ftanh(gg);
            float h = so * ftanh(cs);
            hdst[m * 32] = __float2bfloat16(h);
        }
        __syncthreads();   // all h-stores ordered before the release store
        if (tid == 0)
            asm volatile("st.release.gpu.global.b32 [%0], %1;"
                         :: "l"(myflag), "r"(step + 1) : "memory");
    }
}

// ---- K4: LayerNorm(1024) + ReLU + emission; h layout [dir][t][bh][g][b][32]
__global__ void __launch_bounds__(256) ln_emit_k(const float* __restrict__ lng,
                                                 const float* __restrict__ lnb,
                                                 const float* __restrict__ wout,
                                                 const float* __restrict__ bout) {
    __shared__ float sh[1024];
    __shared__ float rs[8], rs2[8];
    __shared__ float s_mu, s_rstd;
    const int row = blockIdx.x, tid = threadIdx.x;
    const int lane = tid & 31, w = tid >> 5;
    const int t = row >> 5, b = row & 31;
    const int bh = b >> 4, bl = b & 15;
    const __nv_bfloat16* hf = g_hs + ((size_t)t * 2 + bh) * 8192 + bl * 32;
    const __nv_bfloat16* hb = hf + (size_t)TT * 2 * 8192;
    float s = 0.f, s2 = 0.f;
#pragma unroll
    for (int i = 0; i < 4; i++) {
        int idx = tid + i * 256;
        int d = idx & 511;
        int gg = d >> 5, dm = d & 31;
        float x = (idx < 512) ? __bfloat162float(hf[gg * 512 + dm])
                              : __bfloat162float(hb[gg * 512 + dm]);
        sh[idx] = x; s += x; s2 += x * x;
    }
    for (int o = 16; o; o >>= 1) {
        s  += __shfl_down_sync(0xffffffffu, s, o);
        s2 += __shfl_down_sync(0xffffffffu, s2, o);
    }
    if (!lane) { rs[w] = s; rs2[w] = s2; }
    __syncthreads();
    if (!tid) {
        float S = 0.f, S2 = 0.f;
        for (int i = 0; i < 8; i++) { S += rs[i]; S2 += rs2[i]; }
        float mu = S * (1.f / 1024.f);
        s_mu = mu;
        s_rstd = rsqrtf(S2 * (1.f / 1024.f) - mu * mu + 1e-5f);
    }
    __syncthreads();
    float mu = s_mu, rstd = s_rstd;
#pragma unroll
    for (int i = 0; i < 4; i++) {
        int idx = tid + i * 256;
        float x = (sh[idx] - mu) * rstd * lng[idx] + lnb[idx];
        sh[idx] = fmaxf(x, 0.f);
    }
    __syncthreads();
    if (w < 6) {
        float acc = 0.f;
        for (int i = lane; i < 1024; i += 32) acc = fmaf(sh[i], wout[w * 1024 + i], acc);
        for (int o = 16; o; o >>= 1) acc += __shfl_down_sync(0xffffffffu, acc, o);
        if (!lane) g_em[(size_t)row * 6 + w] = acc + bout[w];
    }
}

// ---- K5: CRF (fast-math MUFU exp/log). mask is int32. ----------------------
__global__ void crf_k(const int* __restrict__ tags, const int* __restrict__ mask,
                      const float* __restrict__ st, const float* __restrict__ en,
                      const float* __restrict__ tr, float* __restrict__ out) {
    __shared__ float ll[32];
    const unsigned full = 0xffffffffu;
    const int b = threadIdx.x >> 5, j = threadIdx.x & 31;
    const bool act = j < 6;
    float trc[6];
#pragma unroll
    for (int i = 0; i < 6; i++) trc[i] = tr[i * 6 + (act ? j : 0)];
    float alpha = act ? (st[j] + g_em[b * 6 + j]) : -1e30f;
    int prev = tags[b * TT];
    float score = st[prev] + g_em[b * 6 + prev];
    int cnt = (mask[b * TT] != 0) ? 1 : 0;
    for (int t = 1; t < TT; t++) {
        float m = (mask[b * TT + t] != 0) ? 1.f : 0.f;
        cnt += (int)m;
        int tg = tags[b * TT + t];
        const float* emt = g_em + ((size_t)t * BB + b) * 6;
        score += m * (tr[prev * 6 + tg] + emt[tg]);
        prev = tg;
        float av[6];
#pragma unroll
        for (int i = 0; i < 6; i++) av[i] = __shfl_sync(full, alpha, i);
        if (act) {
            float mx = -1e30f;
#pragma unroll
            for (int i = 0; i < 6; i++) mx = fmaxf(mx, av[i] + trc[i]);
            float sm = 0.f;
#pragma unroll
            for (int i = 0; i < 6; i++) sm += __expf(av[i] + trc[i] - mx);
            float nxt = mx + __logf(sm) + emt[j];
            if (m > 0.f) alpha = nxt;
        }
    }
    int ltag = tags[b * TT + (cnt - 1)];
    float num = score + en[ltag];
    float v = act ? (alpha + en[j]) : -1e30f;
    float mx = v;
    for (int o = 16; o; o >>= 1) mx = fmaxf(mx, __shfl_xor_sync(full, mx, o));
    float sm = act ? __expf(v - mx) : 0.f;
    for (int o = 16; o; o >>= 1) sm += __shfl_xor_sync(full, sm, o);
    float den = mx + __logf(sm);
    if (j == 0) ll[b] = num - den;
    __syncthreads();
    if (threadIdx.x == 0) {
        float s = 0.f;
        for (int i = 0; i < 32; i++) s += ll[i];
        *out = -s * (1.f / 32.f);
    }
}

extern "C" void kernel_launch(void* const* d_in, const int* in_sizes, int n_in,
                              void* d_out, int out_size) {
    const int*   ids  = (const int*)  d_in[0];
    const float* eeg  = (const float*)d_in[1];
    const int*   tags = (const int*)  d_in[2];
    const int*   mask = (const int*)  d_in[3];
    const float* emb  = (const float*)d_in[4];
    const float* wihf = (const float*)d_in[5];
    const float* whhf = (const float*)d_in[6];
    const float* bf   = (const float*)d_in[7];
    const float* wihb = (const float*)d_in[8];
    const float* whhb = (const float*)d_in[9];
    const float* bb   = (const float*)d_in[10];
    const float* lng  = (const float*)d_in[11];
    const float* lnb  = (const float*)d_in[12];
    const float* wout = (const float*)d_in[13];
    const float* bout = (const float*)d_in[14];
    const float* st   = (const float*)d_in[15];
    const float* en   = (const float*)d_in[16];
    const float* tr   = (const float*)d_in[17];
    float* out = (float*)d_out;

    build_x_k<<<NROWS, 128>>>(ids, eeg, emb);
    pack_w_k<<<NG, 128>>>(wihf, wihb, bf, bb);
    gemm_pre_k<<<dim3(64, 256), 128>>>();
    lstm_mma_k<<<64, 256>>>(whhf, whhb);
    ln_emit_k<<<NROWS, 256>>>(lng, lnb, wout, bout);
    crf_k<<<1, 1024>>>(tags, mask, st, en, tr, out);
}